// round 15
// baseline (speedup 1.0000x reference)
#include <cuda_runtime.h>
#include <cstdint>

// CausalQueue: out[b, 0:C]  = (size == D) ? buffer[head, b, :] : 0
//              out[b, C:2C] = x[b, :]
// x: [B,C] f32, buffer: [D,B,C] f32, size/head int32 device scalars.
// D=128, B=2048, C=512. 16 MB traffic; bench floored at ~6.6us, kernel
// time still improvable via latency-hiding pool.
//
// R14: double the TLP of the R13 shape. grid 1024 x 256 (~7 blocks/SM,
// occ ~60%), 2 rows per block, 2 independent front-batched LDG.128 per
// thread. Same minimal dependence structure as R13: unconditional
// data loads addressed by head&127, size consumed only as a uniform
// branch at store time, x-half warps never touch the scalars.

#define D_CAP  128
#define B_DIM  2048
#define C4     128              // float4 per half-row (C=512)
#define ROW4   256              // float4 per output row
#define RPB    2                // rows per block
#define GRID   (B_DIM / RPB)    // 1024

__global__ void __launch_bounds__(256)
causal_queue_kernel(const float4* __restrict__ x,
                    const float4* __restrict__ buffer,
                    const int* __restrict__ size_p,
                    const int* __restrict__ head_p,
                    float4* __restrict__ out)
{
    const int t    = threadIdx.x;        // 0..255 = column in output row
    const int row0 = blockIdx.x * RPB;

    if (t < C4) {
        // ---- past half, column t ----
        const int  size = __ldg(size_p);                 // off the load path
        const int  head = __ldg(head_p) & (D_CAP - 1);   // feeds address, in-bounds

        const float4* src = buffer + (size_t)head * (B_DIM * C4)
                                   + (size_t)row0 * C4 + t;
        float4 v[RPB];
#pragma unroll
        for (int k = 0; k < RPB; k++) v[k] = src[k * C4];   // front-batched

        float4* dst = out + (size_t)row0 * ROW4 + t;
        if (size == D_CAP) {            // uniform across grid: no divergence
#pragma unroll
            for (int k = 0; k < RPB; k++) dst[k * ROW4] = v[k];
        } else {
            const float4 z = make_float4(0.f, 0.f, 0.f, 0.f);
#pragma unroll
            for (int k = 0; k < RPB; k++) dst[k * ROW4] = z;   // no data wait
        }
    } else {
        // ---- x half, column t-128: scalar-free ----
        const float4* src = x + (size_t)row0 * C4 + (t - C4);
        float4 v[RPB];
#pragma unroll
        for (int k = 0; k < RPB; k++) v[k] = src[k * C4];

        float4* dst = out + (size_t)row0 * ROW4 + t;
#pragma unroll
        for (int k = 0; k < RPB; k++) dst[k * ROW4] = v[k];
    }
}

extern "C" void kernel_launch(void* const* d_in, const int* in_sizes, int n_in,
                              void* d_out, int out_size)
{
    const float4* x      = (const float4*)d_in[0];   // [B, C] f32
    const float4* buffer = (const float4*)d_in[1];   // [D, B, C] f32
    const int*    size_p = (const int*)d_in[2];      // scalar
    const int*    head_p = (const int*)d_in[3];      // scalar
    float4*       out    = (float4*)d_out;           // [B, 2C] f32

    causal_queue_kernel<<<GRID, 256>>>(x, buffer, size_p, head_p, out);
}